// round 15
// baseline (speedup 1.0000x reference)
#include <cuda_runtime.h>
#include <cstdint>

// VQBlock via mma.sync tf32x3 with fragment-order pre-layout + exact rescue.
// x [65536, 256] fp32, dict [256, 1024] fp32.
// out[0..N*D) = q_st, out[N*D] = 1.25 * mean((x-q)^2)
//
// R15 = R11/R12 with the g_bfrag overflow FIXED (was declared half-size; bprep
// wrote 1MB past it -> device fault -> "container failed").

#define D_DIM 256
#define K_CODES 1024
#define N_ROWS 65536
#define TM 64
#define TN 128
#define NSTAGES 256                    // 8 chunks x 32 k8-blocks

#define STAGE_BYTES 12288              // A 4096 + B 8192
#define OFF_CNORM   24576              // 4096
#define OFF_SB      28672              // 1024
#define OFF_SS      29696              // 1024
#define OFF_SK      30720              // 1024
#define SMEM_TOTAL  31744
#define GAP_THRESH  2e-3f

__device__ float  g_cnorm[K_CODES];
__device__ float  g_rnorm[N_ROWS];
__device__ float  g_dictT[K_CODES * D_DIM];            // [code][d] fp32
__device__ __align__(16) float g_afrag[2u * N_ROWS * D_DIM];   // frag-order x hi/lo
__device__ __align__(16) float g_bfrag[2 * K_CODES * D_DIM];   // frag-order dict hi/lo (FIXED SIZE)
__device__ int    g_rowk[N_ROWS];
__device__ int    g_flagrows[N_ROWS];
__device__ int    g_nflag;
__device__ double g_sum;

// ---------------------------------------------------------------------------
__device__ __forceinline__ uint32_t smem_u32(const void* p) {
    uint32_t a;
    asm("{ .reg .u64 t; cvta.to.shared.u64 t, %1; cvt.u32.u64 %0, t; }"
        : "=r"(a) : "l"(p));
    return a;
}
__device__ __forceinline__ float tf32_hi(float v) {
    uint32_t r;
    asm("cvt.rna.tf32.f32 %0, %1;" : "=r"(r) : "f"(v));
    return __uint_as_float(r);
}
__device__ __forceinline__ void cp16(uint32_t dst, const void* src) {
    asm volatile("cp.async.cg.shared.global [%0], [%1], 16;"
                 :: "r"(dst), "l"(src) : "memory");
}
__device__ __forceinline__ void mma8(float* c, const uint32_t* a, const uint32_t* b) {
    asm volatile(
        "mma.sync.aligned.m16n8k8.row.col.f32.tf32.tf32.f32 "
        "{%0,%1,%2,%3}, {%4,%5,%6,%7}, {%8,%9}, {%0,%1,%2,%3};"
        : "+f"(c[0]), "+f"(c[1]), "+f"(c[2]), "+f"(c[3])
        : "r"(a[0]), "r"(a[1]), "r"(a[2]), "r"(a[3]), "r"(b[0]), "r"(b[1]));
}

// ---------------------------------------------------------------------------
// colnorm: cnorm (double->fp32) + dictT; inits globals.
__global__ void colnorm_kernel(const float* __restrict__ dict) {
    int gt = blockIdx.x * blockDim.x + threadIdx.x;
    if (gt == 0) { g_sum = 0.0; g_nflag = 0; }
    int warp = gt >> 5;
    int lane = threadIdx.x & 31;
    if (warp >= K_CODES) return;
    double s = 0.0;
    for (int d = lane; d < D_DIM; d += 32) {
        float v = dict[d * K_CODES + warp];
        s += (double)v * v;
        g_dictT[(size_t)warp * D_DIM + d] = v;
    }
#pragma unroll
    for (int o = 16; o > 0; o >>= 1) s += __shfl_xor_sync(0xffffffff, s, o);
    if (lane == 0) g_cnorm[warp] = (float)s;
}

// ---------------------------------------------------------------------------
// aprep: block per 16-row tile. Loads 16x256, computes rnorm (double),
// writes A fragments (hi/lo) in m16n8k8 per-thread order.
__global__ __launch_bounds__(256) void aprep_kernel(const float* __restrict__ x) {
    __shared__ float xs[16][260];
    const int rt = blockIdx.x;          // 0..4095
    const int tid = threadIdx.x;
    const int lane = tid & 31;
    const int wid = tid >> 5;

#pragma unroll
    for (int i = 0; i < 4; i++) {
        int q = i * 256 + tid;
        int r = q >> 6;
        int c4 = q & 63;
        float4 v = *(const float4*)(x + (size_t)(rt * 16 + r) * D_DIM + c4 * 4);
        xs[r][c4 * 4 + 0] = v.x;
        xs[r][c4 * 4 + 1] = v.y;
        xs[r][c4 * 4 + 2] = v.z;
        xs[r][c4 * 4 + 3] = v.w;
    }
    __syncthreads();

    // rnorm: 8 warps, rows wid and wid+8, double accumulation
    for (int rr = wid; rr < 16; rr += 8) {
        double s = 0.0;
        for (int d = lane; d < D_DIM; d += 32) {
            double v = (double)xs[rr][d];
            s += v * v;
        }
#pragma unroll
        for (int o = 16; o > 0; o >>= 1) s += __shfl_xor_sync(0xffffffff, s, o);
        if (lane == 0) g_rnorm[rt * 16 + rr] = (float)s;
    }

    // fragments: t = lane, sub = warp; kb = sub + it*8
    const int t = lane;
    const int r0 = t >> 2;
    const int kq = t & 3;
#pragma unroll
    for (int it = 0; it < 4; it++) {
        int kb = wid + it * 8;
        int k0 = kb * 8 + kq;
        float v0 = xs[r0][k0];
        float v1 = xs[r0 + 8][k0];
        float v2 = xs[r0][k0 + 4];
        float v3 = xs[r0 + 8][k0 + 4];
        float4 hi, lo;
        hi.x = tf32_hi(v0); lo.x = tf32_hi(v0 - hi.x);
        hi.y = tf32_hi(v1); lo.y = tf32_hi(v1 - hi.y);
        hi.z = tf32_hi(v2); lo.z = tf32_hi(v2 - hi.z);
        hi.w = tf32_hi(v3); lo.w = tf32_hi(v3 - hi.w);
        size_t base = (((size_t)(rt * 32 + kb) * 2 + 0) * 32 + t) * 4;
        *(float4*)(g_afrag + base) = hi;
        *(float4*)(g_afrag + base + 128) = lo;   // hl=1
    }
}

// ---------------------------------------------------------------------------
// bprep: block per 8-code tile (ct). Writes B fragments (hi/lo).
__global__ __launch_bounds__(256) void bprep_kernel(const float* __restrict__ dict) {
    const int ct = blockIdx.x;          // 0..127
    const int tid = threadIdx.x;
    const int t = tid & 31;
    const int sub = tid >> 5;
    const int n = ct * 8 + (t >> 2);    // code
    const int kq = t & 3;
#pragma unroll
    for (int it = 0; it < 4; it++) {
        int kb = sub + it * 8;
        float b0 = dict[(kb * 8 + kq) * K_CODES + n];
        float b1 = dict[(kb * 8 + kq + 4) * K_CODES + n];
        float h0 = tf32_hi(b0), l0 = tf32_hi(b0 - h0);
        float h1 = tf32_hi(b1), l1 = tf32_hi(b1 - h1);
        size_t base = (((size_t)(ct * 32 + kb) * 2 + 0) * 32 + t) * 2;
        *(float2*)(g_bfrag + base) = make_float2(h0, h1);
        *(float2*)(g_bfrag + base + 64) = make_float2(l0, l1);  // hl=1
    }
}

// ---------------------------------------------------------------------------
// Main: 256 threads (8 warps as 2x4), tile 64 rows x all 1024 codes.
__global__ __launch_bounds__(256, 2) void vq_tc() {
    extern __shared__ char smem[];
    const uint32_t smu = smem_u32(smem);
    const int tid = threadIdx.x;
    const int lane = tid & 31;
    const int wid = tid >> 5;
    const int wm = wid >> 2;            // 0..1
    const int wn = wid & 3;             // 0..3
    const int gid = lane >> 2;
    const int tig = lane & 3;
    const int row0 = blockIdx.x * TM;

    float* s_cn = (float*)(smem + OFF_CNORM);
    for (int i = tid; i < K_CODES; i += 256) s_cn[i] = g_cnorm[i];

    float rn[4], best[4], sec[4];
    int bestk[4];
#pragma unroll
    for (int bi = 0; bi < 4; bi++) {
        rn[bi] = g_rnorm[row0 + wm * 32 + (bi >> 1) * 16 + (bi & 1) * 8 + gid];
        best[bi] = 3.4e38f;
        sec[bi] = 3.4e38f;
        bestk[bi] = 0;
    }

    auto issue = [&](int s) {
        const int chunk = s >> 5, kb = s & 31;
        const uint32_t sb2 = smu + (uint32_t)(s & 1) * STAGE_BYTES;
        // A: 4096B = 256 cp16, one per thread
        {
            int rtl = tid >> 6, hl = (tid >> 5) & 1, t = tid & 31;
            int rt16g = blockIdx.x * 4 + rtl;
            const float* src = g_afrag
                + (((size_t)(rt16g * 32 + kb) * 2 + hl) * 32 + t) * 4;
            cp16(sb2 + (uint32_t)(((rtl * 2 + hl) * 32 + t) * 16), src);
        }
        // B: 8192B = 512 cp16, two per thread
#pragma unroll
        for (int h = 0; h < 2; h++) {
            int idx = tid + h * 256;
            int ctl = idx >> 5, hl = (idx >> 4) & 1, tp = (idx & 15) * 2;
            int ctg = chunk * 16 + ctl;
            const float* src = g_bfrag
                + (((size_t)(ctg * 32 + kb) * 2 + hl) * 32 + tp) * 2;
            cp16(sb2 + 4096 + (uint32_t)(((ctl * 2 + hl) * 32 + tp) * 8), src);
        }
        asm volatile("cp.async.commit_group;" ::: "memory");
    };

    float acc[2][4][4];
    issue(0);

    for (int s = 0; s < NSTAGES; s++) {
        if (s + 1 < NSTAGES) {
            issue(s + 1);
            asm volatile("cp.async.wait_group 1;" ::: "memory");
        } else {
            asm volatile("cp.async.wait_group 0;" ::: "memory");
        }
        __syncthreads();

        if ((s & 31) == 0) {
#pragma unroll
            for (int ma = 0; ma < 2; ma++)
#pragma unroll
                for (int na = 0; na < 4; na++)
#pragma unroll
                    for (int j = 0; j < 4; j++) acc[ma][na][j] = 0.f;
        }

        const char* sb2 = smem + (s & 1) * STAGE_BYTES;
        uint32_t a_[2][2][4];
#pragma unroll
        for (int ma = 0; ma < 2; ma++)
#pragma unroll
            for (int hl = 0; hl < 2; hl++) {
                int rtl = wm * 2 + ma;
                *(uint4*)a_[ma][hl] =
                    *(const uint4*)(sb2 + ((rtl * 2 + hl) * 32 + lane) * 16);
            }
        uint32_t b_[4][2][2];
#pragma unroll
        for (int na = 0; na < 4; na++)
#pragma unroll
            for (int hl = 0; hl < 2; hl++) {
                int ctl = wn * 4 + na;
                *(uint2*)b_[na][hl] =
                    *(const uint2*)(sb2 + 4096 + ((ctl * 2 + hl) * 32 + lane) * 8);
            }
#pragma unroll
        for (int ma = 0; ma < 2; ma++)
#pragma unroll
            for (int na = 0; na < 4; na++) {
                mma8(acc[ma][na], a_[ma][0], b_[na][0]);
                mma8(acc[ma][na], a_[ma][0], b_[na][1]);
                mma8(acc[ma][na], a_[ma][1], b_[na][0]);
            }
        __syncthreads();

        if ((s & 31) == 31) {
            const int chunk = s >> 5;
#pragma unroll
            for (int ma = 0; ma < 2; ma++)
#pragma unroll
                for (int hl = 0; hl < 2; hl++) {
                    const int bi = ma * 2 + hl;
#pragma unroll
                    for (int na = 0; na < 4; na++) {
                        const int kk = chunk * TN + wn * 32 + na * 8 + tig * 2;
                        float c0 = s_cn[kk], c1 = s_cn[kk + 1];
                        float s0 = acc[ma][na][hl * 2 + 0];
                        float s1 = acc[ma][na][hl * 2 + 1];
                        float d0 = __fsub_rn(__fadd_rn(rn[bi], c0),
                                             __fmul_rn(2.0f, s0));
                        float d1 = __fsub_rn(__fadd_rn(rn[bi], c1),
                                             __fmul_rn(2.0f, s1));
                        if (d0 < best[bi]) { sec[bi] = best[bi]; best[bi] = d0; bestk[bi] = kk; }
                        else if (d0 < sec[bi]) sec[bi] = d0;
                        if (d1 < best[bi]) { sec[bi] = best[bi]; best[bi] = d1; bestk[bi] = kk + 1; }
                        else if (d1 < sec[bi]) sec[bi] = d1;
                    }
                }
        }
    }

    // --- top-2 argmin reduce: over tig lanes, then over wn ---
    float* sb = (float*)(smem + OFF_SB);
    float* ssm = (float*)(smem + OFF_SS);
    int*   sk = (int*)(smem + OFF_SK);
#pragma unroll
    for (int bi = 0; bi < 4; bi++) {
        float b = best[bi], s2 = sec[bi];
        int bk = bestk[bi];
#pragma unroll
        for (int m = 1; m <= 2; m <<= 1) {
            float ob = __shfl_xor_sync(0xffffffff, b, m);
            float os = __shfl_xor_sync(0xffffffff, s2, m);
            int obk = __shfl_xor_sync(0xffffffff, bk, m);
            float ns = fminf(fmaxf(b, ob), fminf(s2, os));
            if (ob < b || (ob == b && obk < bk)) { b = ob; bk = obk; }
            s2 = ns;
        }
        if (tig == 0) {
            int row = wm * 32 + (bi >> 1) * 16 + (bi & 1) * 8 + gid;
            sb[row * 4 + wn] = b;
            ssm[row * 4 + wn] = s2;
            sk[row * 4 + wn] = bk;
        }
    }
    __syncthreads();
    if (tid < TM) {
        float b = sb[tid * 4], s2 = ssm[tid * 4];
        int bk = sk[tid * 4];
#pragma unroll
        for (int w = 1; w < 4; w++) {
            float v = sb[tid * 4 + w];
            float vs = ssm[tid * 4 + w];
            int vk = sk[tid * 4 + w];
            float ns = fminf(fmaxf(b, v), fminf(s2, vs));
            if (v < b || (v == b && vk < bk)) { b = v; bk = vk; }
            s2 = ns;
        }
        int row = row0 + tid;
        g_rowk[row] = bk;
        if (s2 - b < GAP_THRESH) {
            int i = atomicAdd(&g_nflag, 1);
            g_flagrows[i] = row;
        }
    }
}

// ---------------------------------------------------------------------------
// Rescue: exact-R2 recompute for flagged rows.
__global__ void rescue_kernel(const float* __restrict__ x) {
    __shared__ float srow[8][D_DIM];
    const int lane = threadIdx.x & 31;
    const int wl = threadIdx.x >> 5;
    const int wglobal = (blockIdx.x * blockDim.x + threadIdx.x) >> 5;
    const int nw = (gridDim.x * blockDim.x) >> 5;
    const int nf = g_nflag;

    for (int i = wglobal; i < nf; i += nw) {
        const int row = g_flagrows[i];
        ((float4*)srow[wl])[lane] = ((const float4*)(x + (size_t)row * D_DIM))[lane];
        ((float4*)srow[wl])[lane + 32] = ((const float4*)(x + (size_t)row * D_DIM))[lane + 32];
        __syncwarp();
        const float r = g_rnorm[row];
        float best = 3.4e38f;
        int bk = 0;
        for (int j = 0; j < 32; j++) {
            const int k = lane + j * 32;
            const float* dp = g_dictT + (size_t)k * D_DIM;
            float sim = 0.f;
#pragma unroll 8
            for (int d = 0; d < D_DIM; d++)
                sim = __fmaf_rn(srow[wl][d], dp[d], sim);
            float dist = __fsub_rn(__fadd_rn(r, g_cnorm[k]),
                                   __fmul_rn(2.0f, sim));
            if (dist < best) { best = dist; bk = k; }
        }
#pragma unroll
        for (int m = 1; m < 32; m <<= 1) {
            float ob = __shfl_xor_sync(0xffffffff, best, m);
            int obk = __shfl_xor_sync(0xffffffff, bk, m);
            if (ob < best || (ob == best && obk < bk)) { best = ob; bk = obk; }
        }
        if (lane == 0) g_rowk[row] = bk;
        __syncwarp();
    }
}

// ---------------------------------------------------------------------------
__global__ __launch_bounds__(256) void output_kernel(const float* __restrict__ x,
                                                     float* __restrict__ out) {
    const int tid = threadIdx.x;
    double ls = 0.0;
    for (int r = blockIdx.x; r < N_ROWS; r += gridDim.x) {
        int k = g_rowk[r];
        float qv = 0.5f * g_dictT[(size_t)k * D_DIM + tid];
        float xv = x[(size_t)r * D_DIM + tid];
        out[(size_t)r * D_DIM + tid] = __fadd_rn(xv, __fsub_rn(qv, xv));
        float df = xv - qv;
        ls += (double)df * (double)df;
    }
    __shared__ double sred[256];
    sred[tid] = ls;
    __syncthreads();
    for (int s = 128; s > 0; s >>= 1) {
        if (tid < s) sred[tid] += sred[tid + s];
        __syncthreads();
    }
    if (tid == 0) atomicAdd(&g_sum, sred[0]);
}

// ---------------------------------------------------------------------------
__global__ void finalize_kernel(float* out, long long total, int loss_idx) {
    out[loss_idx] = (float)(1.25 * g_sum / (double)total);
}

// ---------------------------------------------------------------------------
extern "C" void kernel_launch(void* const* d_in, const int* in_sizes, int n_in,
                              void* d_out, int out_size) {
    const float* x    = (const float*)d_in[0];
    const float* dict = (const float*)d_in[1];
    float* out = (float*)d_out;

    int Nel = in_sizes[0];             // 16777216
    int n_tiles = Nel / D_DIM / TM;    // 1024

    cudaFuncSetAttribute(vq_tc, cudaFuncAttributeMaxDynamicSharedMemorySize,
                         SMEM_TOTAL);

    colnorm_kernel<<<(K_CODES * 32 + 255) / 256, 256>>>(dict);
    aprep_kernel<<<N_ROWS / 16, 256>>>(x);
    bprep_kernel<<<K_CODES / 8, 256>>>(dict);
    vq_tc<<<n_tiles, 256, SMEM_TOTAL>>>();
    rescue_kernel<<<256, 256>>>(x);
    output_kernel<<<1024, 256>>>(x, out);
    if (out_size > Nel) {
        finalize_kernel<<<1, 1>>>(out, (long long)Nel, out_size - 1);
    }
}

// round 17
// speedup vs baseline: 2.0581x; 2.0581x over previous
#include <cuda_runtime.h>
#include <cstdio>
#include <cstdint>

// VQBlock via mma.sync tf32x3 with fragment-order pre-layout + exact rescue.
// x [65536, 256] fp32, dict [256, 1024] fp32.
// out[0..N*D) = q_st, out[N*D] = 1.25 * mean((x-q)^2)
//
// R16 = R15 with rescue_kernel rewritten block-per-row (bounded cost even at
// nf=65536) + NFLAG diagnostic print in finalize.

#define D_DIM 256
#define K_CODES 1024
#define N_ROWS 65536
#define TM 64
#define TN 128
#define NSTAGES 256                    // 8 chunks x 32 k8-blocks

#define STAGE_BYTES 12288              // A 4096 + B 8192
#define OFF_CNORM   24576              // 4096
#define OFF_SB      28672              // 1024
#define OFF_SS      29696              // 1024
#define OFF_SK      30720              // 1024
#define SMEM_TOTAL  31744
#define GAP_THRESH  2e-3f

__device__ float  g_cnorm[K_CODES];
__device__ float  g_rnorm[N_ROWS];
__device__ float  g_dictT[K_CODES * D_DIM];            // [code][d] fp32
__device__ __align__(16) float g_afrag[2u * N_ROWS * D_DIM];   // frag-order x hi/lo
__device__ __align__(16) float g_bfrag[2 * K_CODES * D_DIM];   // frag-order dict hi/lo
__device__ int    g_rowk[N_ROWS];
__device__ int    g_flagrows[N_ROWS];
__device__ int    g_nflag;
__device__ double g_sum;

// ---------------------------------------------------------------------------
__device__ __forceinline__ uint32_t smem_u32(const void* p) {
    uint32_t a;
    asm("{ .reg .u64 t; cvta.to.shared.u64 t, %1; cvt.u32.u64 %0, t; }"
        : "=r"(a) : "l"(p));
    return a;
}
__device__ __forceinline__ float tf32_hi(float v) {
    uint32_t r;
    asm("cvt.rna.tf32.f32 %0, %1;" : "=r"(r) : "f"(v));
    return __uint_as_float(r);
}
__device__ __forceinline__ void cp16(uint32_t dst, const void* src) {
    asm volatile("cp.async.cg.shared.global [%0], [%1], 16;"
                 :: "r"(dst), "l"(src) : "memory");
}
__device__ __forceinline__ void mma8(float* c, const uint32_t* a, const uint32_t* b) {
    asm volatile(
        "mma.sync.aligned.m16n8k8.row.col.f32.tf32.tf32.f32 "
        "{%0,%1,%2,%3}, {%4,%5,%6,%7}, {%8,%9}, {%0,%1,%2,%3};"
        : "+f"(c[0]), "+f"(c[1]), "+f"(c[2]), "+f"(c[3])
        : "r"(a[0]), "r"(a[1]), "r"(a[2]), "r"(a[3]), "r"(b[0]), "r"(b[1]));
}

// ---------------------------------------------------------------------------
// colnorm: cnorm (double->fp32) + dictT; inits globals.
__global__ void colnorm_kernel(const float* __restrict__ dict) {
    int gt = blockIdx.x * blockDim.x + threadIdx.x;
    if (gt == 0) { g_sum = 0.0; g_nflag = 0; }
    int warp = gt >> 5;
    int lane = threadIdx.x & 31;
    if (warp >= K_CODES) return;
    double s = 0.0;
    for (int d = lane; d < D_DIM; d += 32) {
        float v = dict[d * K_CODES + warp];
        s += (double)v * v;
        g_dictT[(size_t)warp * D_DIM + d] = v;
    }
#pragma unroll
    for (int o = 16; o > 0; o >>= 1) s += __shfl_xor_sync(0xffffffff, s, o);
    if (lane == 0) g_cnorm[warp] = (float)s;
}

// ---------------------------------------------------------------------------
// aprep: block per 16-row tile. Loads 16x256, computes rnorm (double),
// writes A fragments (hi/lo) in m16n8k8 per-thread order.
__global__ __launch_bounds__(256) void aprep_kernel(const float* __restrict__ x) {
    __shared__ float xs[16][260];
    const int rt = blockIdx.x;          // 0..4095
    const int tid = threadIdx.x;
    const int lane = tid & 31;
    const int wid = tid >> 5;

#pragma unroll
    for (int i = 0; i < 4; i++) {
        int q = i * 256 + tid;
        int r = q >> 6;
        int c4 = q & 63;
        float4 v = *(const float4*)(x + (size_t)(rt * 16 + r) * D_DIM + c4 * 4);
        xs[r][c4 * 4 + 0] = v.x;
        xs[r][c4 * 4 + 1] = v.y;
        xs[r][c4 * 4 + 2] = v.z;
        xs[r][c4 * 4 + 3] = v.w;
    }
    __syncthreads();

    for (int rr = wid; rr < 16; rr += 8) {
        double s = 0.0;
        for (int d = lane; d < D_DIM; d += 32) {
            double v = (double)xs[rr][d];
            s += v * v;
        }
#pragma unroll
        for (int o = 16; o > 0; o >>= 1) s += __shfl_xor_sync(0xffffffff, s, o);
        if (lane == 0) g_rnorm[rt * 16 + rr] = (float)s;
    }

    const int t = lane;
    const int r0 = t >> 2;
    const int kq = t & 3;
#pragma unroll
    for (int it = 0; it < 4; it++) {
        int kb = wid + it * 8;
        int k0 = kb * 8 + kq;
        float v0 = xs[r0][k0];
        float v1 = xs[r0 + 8][k0];
        float v2 = xs[r0][k0 + 4];
        float v3 = xs[r0 + 8][k0 + 4];
        float4 hi, lo;
        hi.x = tf32_hi(v0); lo.x = tf32_hi(v0 - hi.x);
        hi.y = tf32_hi(v1); lo.y = tf32_hi(v1 - hi.y);
        hi.z = tf32_hi(v2); lo.z = tf32_hi(v2 - hi.z);
        hi.w = tf32_hi(v3); lo.w = tf32_hi(v3 - hi.w);
        size_t base = (((size_t)(rt * 32 + kb) * 2 + 0) * 32 + t) * 4;
        *(float4*)(g_afrag + base) = hi;
        *(float4*)(g_afrag + base + 128) = lo;   // hl=1
    }
}

// ---------------------------------------------------------------------------
// bprep: block per 8-code tile (ct). Writes B fragments (hi/lo).
__global__ __launch_bounds__(256) void bprep_kernel(const float* __restrict__ dict) {
    const int ct = blockIdx.x;          // 0..127
    const int tid = threadIdx.x;
    const int t = tid & 31;
    const int sub = tid >> 5;
    const int n = ct * 8 + (t >> 2);    // code
    const int kq = t & 3;
#pragma unroll
    for (int it = 0; it < 4; it++) {
        int kb = sub + it * 8;
        float b0 = dict[(kb * 8 + kq) * K_CODES + n];
        float b1 = dict[(kb * 8 + kq + 4) * K_CODES + n];
        float h0 = tf32_hi(b0), l0 = tf32_hi(b0 - h0);
        float h1 = tf32_hi(b1), l1 = tf32_hi(b1 - h1);
        size_t base = (((size_t)(ct * 32 + kb) * 2 + 0) * 32 + t) * 2;
        *(float2*)(g_bfrag + base) = make_float2(h0, h1);
        *(float2*)(g_bfrag + base + 64) = make_float2(l0, l1);  // hl=1
    }
}

// ---------------------------------------------------------------------------
// Main: 256 threads (8 warps as 2x4), tile 64 rows x all 1024 codes.
__global__ __launch_bounds__(256, 2) void vq_tc() {
    extern __shared__ char smem[];
    const uint32_t smu = smem_u32(smem);
    const int tid = threadIdx.x;
    const int lane = tid & 31;
    const int wid = tid >> 5;
    const int wm = wid >> 2;            // 0..1
    const int wn = wid & 3;             // 0..3
    const int gid = lane >> 2;
    const int tig = lane & 3;
    const int row0 = blockIdx.x * TM;

    float* s_cn = (float*)(smem + OFF_CNORM);
    for (int i = tid; i < K_CODES; i += 256) s_cn[i] = g_cnorm[i];

    float rn[4], best[4], sec[4];
    int bestk[4];
#pragma unroll
    for (int bi = 0; bi < 4; bi++) {
        rn[bi] = g_rnorm[row0 + wm * 32 + (bi >> 1) * 16 + (bi & 1) * 8 + gid];
        best[bi] = 3.4e38f;
        sec[bi] = 3.4e38f;
        bestk[bi] = 0;
    }

    auto issue = [&](int s) {
        const int chunk = s >> 5, kb = s & 31;
        const uint32_t sb2 = smu + (uint32_t)(s & 1) * STAGE_BYTES;
        {
            int rtl = tid >> 6, hl = (tid >> 5) & 1, t = tid & 31;
            int rt16g = blockIdx.x * 4 + rtl;
            const float* src = g_afrag
                + (((size_t)(rt16g * 32 + kb) * 2 + hl) * 32 + t) * 4;
            cp16(sb2 + (uint32_t)(((rtl * 2 + hl) * 32 + t) * 16), src);
        }
#pragma unroll
        for (int h = 0; h < 2; h++) {
            int idx = tid + h * 256;
            int ctl = idx >> 5, hl = (idx >> 4) & 1, tp = (idx & 15) * 2;
            int ctg = chunk * 16 + ctl;
            const float* src = g_bfrag
                + (((size_t)(ctg * 32 + kb) * 2 + hl) * 32 + tp) * 2;
            cp16(sb2 + 4096 + (uint32_t)(((ctl * 2 + hl) * 32 + tp) * 8), src);
        }
        asm volatile("cp.async.commit_group;" ::: "memory");
    };

    float acc[2][4][4];
    issue(0);

    for (int s = 0; s < NSTAGES; s++) {
        if (s + 1 < NSTAGES) {
            issue(s + 1);
            asm volatile("cp.async.wait_group 1;" ::: "memory");
        } else {
            asm volatile("cp.async.wait_group 0;" ::: "memory");
        }
        __syncthreads();

        if ((s & 31) == 0) {
#pragma unroll
            for (int ma = 0; ma < 2; ma++)
#pragma unroll
                for (int na = 0; na < 4; na++)
#pragma unroll
                    for (int j = 0; j < 4; j++) acc[ma][na][j] = 0.f;
        }

        const char* sb2 = smem + (s & 1) * STAGE_BYTES;
        uint32_t a_[2][2][4];
#pragma unroll
        for (int ma = 0; ma < 2; ma++)
#pragma unroll
            for (int hl = 0; hl < 2; hl++) {
                int rtl = wm * 2 + ma;
                *(uint4*)a_[ma][hl] =
                    *(const uint4*)(sb2 + ((rtl * 2 + hl) * 32 + lane) * 16);
            }
        uint32_t b_[4][2][2];
#pragma unroll
        for (int na = 0; na < 4; na++)
#pragma unroll
            for (int hl = 0; hl < 2; hl++) {
                int ctl = wn * 4 + na;
                *(uint2*)b_[na][hl] =
                    *(const uint2*)(sb2 + 4096 + ((ctl * 2 + hl) * 32 + lane) * 8);
            }
#pragma unroll
        for (int ma = 0; ma < 2; ma++)
#pragma unroll
            for (int na = 0; na < 4; na++) {
                mma8(acc[ma][na], a_[ma][0], b_[na][0]);
                mma8(acc[ma][na], a_[ma][0], b_[na][1]);
                mma8(acc[ma][na], a_[ma][1], b_[na][0]);
            }
        __syncthreads();

        if ((s & 31) == 31) {
            const int chunk = s >> 5;
#pragma unroll
            for (int ma = 0; ma < 2; ma++)
#pragma unroll
                for (int hl = 0; hl < 2; hl++) {
                    const int bi = ma * 2 + hl;
#pragma unroll
                    for (int na = 0; na < 4; na++) {
                        const int kk = chunk * TN + wn * 32 + na * 8 + tig * 2;
                        float c0 = s_cn[kk], c1 = s_cn[kk + 1];
                        float s0 = acc[ma][na][hl * 2 + 0];
                        float s1 = acc[ma][na][hl * 2 + 1];
                        float d0 = __fsub_rn(__fadd_rn(rn[bi], c0),
                                             __fmul_rn(2.0f, s0));
                        float d1 = __fsub_rn(__fadd_rn(rn[bi], c1),
                                             __fmul_rn(2.0f, s1));
                        if (d0 < best[bi]) { sec[bi] = best[bi]; best[bi] = d0; bestk[bi] = kk; }
                        else if (d0 < sec[bi]) sec[bi] = d0;
                        if (d1 < best[bi]) { sec[bi] = best[bi]; best[bi] = d1; bestk[bi] = kk + 1; }
                        else if (d1 < sec[bi]) sec[bi] = d1;
                    }
                }
        }
    }

    // --- top-2 argmin reduce: over tig lanes, then over wn ---
    float* sb = (float*)(smem + OFF_SB);
    float* ssm = (float*)(smem + OFF_SS);
    int*   sk = (int*)(smem + OFF_SK);
#pragma unroll
    for (int bi = 0; bi < 4; bi++) {
        float b = best[bi], s2 = sec[bi];
        int bk = bestk[bi];
#pragma unroll
        for (int m = 1; m <= 2; m <<= 1) {
            float ob = __shfl_xor_sync(0xffffffff, b, m);
            float os = __shfl_xor_sync(0xffffffff, s2, m);
            int obk = __shfl_xor_sync(0xffffffff, bk, m);
            float ns = fminf(fmaxf(b, ob), fminf(s2, os));
            if (ob < b || (ob == b && obk < bk)) { b = ob; bk = obk; }
            s2 = ns;
        }
        if (tig == 0) {
            int row = wm * 32 + (bi >> 1) * 16 + (bi & 1) * 8 + gid;
            sb[row * 4 + wn] = b;
            ssm[row * 4 + wn] = s2;
            sk[row * 4 + wn] = bk;
        }
    }
    __syncthreads();
    if (tid < TM) {
        float b = sb[tid * 4], s2 = ssm[tid * 4];
        int bk = sk[tid * 4];
#pragma unroll
        for (int w = 1; w < 4; w++) {
            float v = sb[tid * 4 + w];
            float vs = ssm[tid * 4 + w];
            int vk = sk[tid * 4 + w];
            float ns = fminf(fmaxf(b, v), fminf(s2, vs));
            if (v < b || (v == b && vk < bk)) { b = v; bk = vk; }
            s2 = ns;
        }
        int row = row0 + tid;
        g_rowk[row] = bk;
        if (s2 - b < GAP_THRESH) {
            int i = atomicAdd(&g_nflag, 1);
            g_flagrows[i] = row;
        }
    }
}

// ---------------------------------------------------------------------------
// Rescue v2: block per flagged row, 256 threads, coalesced dict reads.
// Exact R2 semantics: serial d-ascending fp32 FMA, dist = fl(fl(r+c)-2*sim),
// first-index tie-break.
__global__ __launch_bounds__(256) void rescue_kernel(const float* __restrict__ x,
                                                     const float* __restrict__ dict) {
    __shared__ float srow[D_DIM];
    __shared__ float rb[256];
    __shared__ int   rk[256];
    const int tid = threadIdx.x;
    const int nf = g_nflag;

    for (int i = blockIdx.x; i < nf; i += gridDim.x) {
        const int row = g_flagrows[i];
        srow[tid] = x[(size_t)row * D_DIM + tid];
        __syncthreads();
        const float r = g_rnorm[row];
        float best = 3.4e38f;
        int bk = 0;
#pragma unroll
        for (int p = 0; p < 4; p++) {
            const int k = p * 256 + tid;
            float sim = 0.f;
#pragma unroll 8
            for (int d = 0; d < D_DIM; d++)
                sim = __fmaf_rn(srow[d], dict[d * K_CODES + k], sim);
            float dist = __fsub_rn(__fadd_rn(r, g_cnorm[k]),
                                   __fmul_rn(2.0f, sim));
            if (dist < best) { best = dist; bk = k; }   // ascending k => first-index
        }
        rb[tid] = best;
        rk[tid] = bk;
        __syncthreads();
        for (int s = 128; s > 0; s >>= 1) {
            if (tid < s) {
                float v = rb[tid + s];
                int vk = rk[tid + s];
                if (v < rb[tid] || (v == rb[tid] && vk < rk[tid])) {
                    rb[tid] = v;
                    rk[tid] = vk;
                }
            }
            __syncthreads();
        }
        if (tid == 0) g_rowk[row] = rk[0];
        __syncthreads();
    }
}

// ---------------------------------------------------------------------------
__global__ __launch_bounds__(256) void output_kernel(const float* __restrict__ x,
                                                     float* __restrict__ out) {
    const int tid = threadIdx.x;
    double ls = 0.0;
    for (int r = blockIdx.x; r < N_ROWS; r += gridDim.x) {
        int k = g_rowk[r];
        float qv = 0.5f * g_dictT[(size_t)k * D_DIM + tid];
        float xv = x[(size_t)r * D_DIM + tid];
        out[(size_t)r * D_DIM + tid] = __fadd_rn(xv, __fsub_rn(qv, xv));
        float df = xv - qv;
        ls += (double)df * (double)df;
    }
    __shared__ double sred[256];
    sred[tid] = ls;
    __syncthreads();
    for (int s = 128; s > 0; s >>= 1) {
        if (tid < s) sred[tid] += sred[tid + s];
        __syncthreads();
    }
    if (tid == 0) atomicAdd(&g_sum, sred[0]);
}

// ---------------------------------------------------------------------------
__global__ void finalize_kernel(float* out, long long total, int loss_idx) {
    printf("NFLAG %d\n", g_nflag);
    out[loss_idx] = (float)(1.25 * g_sum / (double)total);
}

// ---------------------------------------------------------------------------
extern "C" void kernel_launch(void* const* d_in, const int* in_sizes, int n_in,
                              void* d_out, int out_size) {
    const float* x    = (const float*)d_in[0];
    const float* dict = (const float*)d_in[1];
    float* out = (float*)d_out;

    int Nel = in_sizes[0];             // 16777216
    int n_tiles = Nel / D_DIM / TM;    // 1024

    cudaFuncSetAttribute(vq_tc, cudaFuncAttributeMaxDynamicSharedMemorySize,
                         SMEM_TOTAL);

    colnorm_kernel<<<(K_CODES * 32 + 255) / 256, 256>>>(dict);
    aprep_kernel<<<N_ROWS / 16, 256>>>(x);
    bprep_kernel<<<K_CODES / 8, 256>>>(dict);
    vq_tc<<<n_tiles, 256, SMEM_TOTAL>>>();
    rescue_kernel<<<2048, 256>>>(x, dict);
    output_kernel<<<1024, 256>>>(x, out);
    if (out_size > Nel) {
        finalize_kernel<<<1, 1>>>(out, (long long)Nel, out_size - 1);
    }
}